// round 7
// baseline (speedup 1.0000x reference)
#include <cuda_runtime.h>
#include <cstdint>

#define NPTS 1000000
#define NC   128
#define NG   100000

#define PTS_PER_CTA 64          // 64 points * 512B = 32KB smem tile
#define ACCUM_THREADS 256

// scratch: group sums + counts (zeroed each launch; graph-replay safe)
__device__ float4 g_sums[(size_t)NG * 32];   // 51.2 MB, [G][32] float4
__device__ float  g_counts[NG];

__global__ void zero_kernel() {
    size_t i = (size_t)blockIdx.x * blockDim.x + threadIdx.x;
    if (i < (size_t)NG * 32) g_sums[i] = make_float4(0.f, 0.f, 0.f, 0.f);
    if (i < NG) g_counts[i] = 0.0f;
}

__device__ __forceinline__ uint32_t smem_u32(const void* p) {
    uint32_t a;
    asm("{ .reg .u64 t; cvta.to.shared.u64 t, %1; cvt.u32.u64 %0, t; }"
        : "=r"(a) : "l"(p));
    return a;
}

// Stage a tile of points in SMEM, then one 512B L2-side bulk fp32 reduction per point.
__global__ __launch_bounds__(ACCUM_THREADS)
void accum_kernel(const float4* __restrict__ feat,
                  const int* __restrict__ gid) {
    __shared__ float4 tile[PTS_PER_CTA * 32];   // 32 KB
    int tid = threadIdx.x;
    size_t p0 = (size_t)blockIdx.x * PTS_PER_CTA;

    // cooperative coalesced load: 2048 float4 across 256 threads (8 each)
    const float4* src = feat + p0 * 32;
#pragma unroll
    for (int j = 0; j < (PTS_PER_CTA * 32) / ACCUM_THREADS; j++) {
        int idx = tid + j * ACCUM_THREADS;
        tile[idx] = __ldcs(&src[idx]);          // streaming: don't pollute L2
    }
    __syncthreads();

    // threads 0..63: one 512-byte bulk reduction per point + count red
    if (tid < PTS_PER_CTA) {
        int g = gid[p0 + tid];
        g = (g < 0) ? 0 : (g >= NG ? NG - 1 : g);
        float* dst = reinterpret_cast<float*>(g_sums + (size_t)g * 32);
        uint32_t s = smem_u32(&tile[tid * 32]);
        asm volatile(
            "cp.reduce.async.bulk.global.shared::cta.bulk_group.add.f32 [%0], [%1], %2;"
            :: "l"(dst), "r"(s), "r"(512) : "memory");
        atomicAdd(&g_counts[g], 1.0f);          // no return -> REDG
        asm volatile("cp.async.bulk.commit_group;" ::: "memory");
        asm volatile("cp.async.bulk.wait_group 0;" ::: "memory");
    }
}

// fused mean + gather: out[p] = sums[g] * 1/max(count[g],1); 8 points per warp
__global__ void gather_kernel(const int* __restrict__ gid,
                              float4* __restrict__ out) {
    int warp = (int)((blockIdx.x * (size_t)blockDim.x + threadIdx.x) >> 5);
    int lane = threadIdx.x & 31;
    int p0 = warp * 8;
    if (p0 >= NPTS) return;

    int g[8];
#pragma unroll
    for (int j = 0; j < 8; j++) {
        int t = __ldg(&gid[p0 + j]);
        g[j] = (t < 0) ? 0 : (t >= NG ? NG - 1 : t);
    }

    float4 v[8];
#pragma unroll
    for (int j = 0; j < 8; j++) v[j] = g_sums[(size_t)g[j] * 32 + lane];  // L2-resident

    float rinv[8];
#pragma unroll
    for (int j = 0; j < 8; j++) rinv[j] = __frcp_rn(fmaxf(g_counts[g[j]], 1.0f));

#pragma unroll
    for (int j = 0; j < 8; j++) {
        float4 r = make_float4(v[j].x * rinv[j], v[j].y * rinv[j],
                               v[j].z * rinv[j], v[j].w * rinv[j]);
        __stcs(&out[(size_t)(p0 + j) * 32 + lane], r);  // streaming store
    }
}

extern "C" void kernel_launch(void* const* d_in, const int* in_sizes, int n_in,
                              void* d_out, int out_size) {
    // inputs: [0] ref_bxyz f32 [N,4] (unused), [1] ref_feat f32 [N,128],
    //         [2] group_ids int32 [N]
    const float4* feat = (const float4*)d_in[1];
    const int*    gid  = (const int*)d_in[2];
    float4*       out  = (float4*)d_out;

    const int T = 256;
    size_t zero_elems = (size_t)NG * 32;  // float4 elements
    zero_kernel<<<(unsigned)((zero_elems + T - 1) / T), T>>>();

    // accum: one CTA per 64 points
    unsigned accum_blocks = (NPTS + PTS_PER_CTA - 1) / PTS_PER_CTA;  // 15625
    accum_kernel<<<accum_blocks, ACCUM_THREADS>>>(feat, gid);

    // gather: one warp per 8 points
    size_t warps = (NPTS + 7) / 8;
    size_t threads = warps * 32;
    gather_kernel<<<(unsigned)((threads + T - 1) / T), T>>>(gid, out);
}

// round 8
// speedup vs baseline: 1.4008x; 1.4008x over previous
#include <cuda_runtime.h>
#include <cstdint>

#define NPTS 1000000
#define NC   128
#define NG   100000

// scratch: group sums + counts (zeroed each launch; graph-replay safe)
__device__ float4 g_sums[(size_t)NG * 32];   // 51.2 MB, [G][32] float4
__device__ float  g_counts[NG];

__global__ void zero_kernel() {
    size_t i = (size_t)blockIdx.x * blockDim.x + threadIdx.x;
    if (i < (size_t)NG * 32) g_sums[i] = make_float4(0.f, 0.f, 0.f, 0.f);
    if (i < NG) g_counts[i] = 0.0f;
}

__device__ __forceinline__ void red_add_v4(float* addr, float4 v) {
    asm volatile("red.global.add.v4.f32 [%0], {%1, %2, %3, %4};"
                 :: "l"(addr), "f"(v.x), "f"(v.y), "f"(v.z), "f"(v.w)
                 : "memory");
}

// one warp per 8 points; lane l handles float4 chunk l of each point
__global__ void accum_kernel(const float4* __restrict__ feat,
                             const int* __restrict__ gid) {
    int warp = (int)((blockIdx.x * (size_t)blockDim.x + threadIdx.x) >> 5);
    int lane = threadIdx.x & 31;
    int p0 = warp * 8;
    if (p0 >= NPTS) return;

    int g[8];
#pragma unroll
    for (int j = 0; j < 8; j++) {
        int t = __ldg(&gid[p0 + j]);
        g[j] = (t < 0) ? 0 : (t >= NG ? NG - 1 : t);
    }

    float4 v[8];
#pragma unroll
    for (int j = 0; j < 8; j++)
        v[j] = __ldcs(&feat[(size_t)(p0 + j) * 32 + lane]);  // streaming read

#pragma unroll
    for (int j = 0; j < 8; j++) {
        float* base = reinterpret_cast<float*>(g_sums + (size_t)g[j] * 32 + lane);
        red_add_v4(base, v[j]);
    }
    if (lane == 0) {
#pragma unroll
        for (int j = 0; j < 8; j++) atomicAdd(&g_counts[g[j]], 1.0f);  // REDG
    }
}

// fused mean + gather: out[p] = sums[g] * 1/max(count[g],1); 8 points per warp
__global__ void gather_kernel(const int* __restrict__ gid,
                              float4* __restrict__ out) {
    int warp = (int)((blockIdx.x * (size_t)blockDim.x + threadIdx.x) >> 5);
    int lane = threadIdx.x & 31;
    int p0 = warp * 8;
    if (p0 >= NPTS) return;

    int g[8];
#pragma unroll
    for (int j = 0; j < 8; j++) {
        int t = __ldg(&gid[p0 + j]);
        g[j] = (t < 0) ? 0 : (t >= NG ? NG - 1 : t);
    }

    float4 v[8];
#pragma unroll
    for (int j = 0; j < 8; j++) v[j] = g_sums[(size_t)g[j] * 32 + lane];  // L2-resident

    float rinv[8];
#pragma unroll
    for (int j = 0; j < 8; j++) rinv[j] = __frcp_rn(fmaxf(g_counts[g[j]], 1.0f));

#pragma unroll
    for (int j = 0; j < 8; j++) {
        float4 r = make_float4(v[j].x * rinv[j], v[j].y * rinv[j],
                               v[j].z * rinv[j], v[j].w * rinv[j]);
        __stcs(&out[(size_t)(p0 + j) * 32 + lane], r);  // streaming store
    }
}

extern "C" void kernel_launch(void* const* d_in, const int* in_sizes, int n_in,
                              void* d_out, int out_size) {
    // inputs: [0] ref_bxyz f32 [N,4] (unused), [1] ref_feat f32 [N,128],
    //         [2] group_ids int32 [N]
    const float4* feat = (const float4*)d_in[1];
    const int*    gid  = (const int*)d_in[2];
    float4*       out  = (float4*)d_out;

    const int T = 256;
    size_t zero_elems = (size_t)NG * 32;  // float4 elements
    zero_kernel<<<(unsigned)((zero_elems + T - 1) / T), T>>>();

    // one warp per 8 points
    size_t warps = (NPTS + 7) / 8;
    size_t threads = warps * 32;
    unsigned blocks = (unsigned)((threads + T - 1) / T);
    accum_kernel<<<blocks, T>>>(feat, gid);
    gather_kernel<<<blocks, T>>>(gid, out);
}